// round 16
// baseline (speedup 1.0000x reference)
#include <cuda_runtime.h>
#include <cuda_fp16.h>
#include <cstdint>

// ---------------------------------------------------------------------------
// SelfAttention (B=4, S=256, HID=1024, NH=8) -> effective attn seq 2048, HD=128
// Round 16: delete Vt + transpose_v. Flash GEMM2 reads V directly from QKV
// (k-major [key][hd]) via ldmatrix.x4.trans; K and V stream chunks now share
// one addressing form. Everything else = R15. fp16 mma.m16n8k16, f32 acc.
// ---------------------------------------------------------------------------

__device__ __half g_QKV[25165824];  // Q | K | V, each (4,2048,8,128)
__device__ __half g_Ctx[8388608];
__device__ float  g_P[4194304];     // FC split-K partials
__device__ __half g_inh[3145728];   // fp16 query/key_/value
__device__ __half g_Wh[33554432];   // fp16 Wq,Wk,Wv,Wfc
__device__ float  g_bias[24576];    // bq | bk | bv

__device__ __forceinline__ uint32_t smem_u32(const void* p) {
    uint32_t a;
    asm("{ .reg .u64 t; cvta.to.shared.u64 t, %1; cvt.u32.u64 %0, t; }"
        : "=r"(a) : "l"(p));
    return a;
}
__device__ __forceinline__ void mma_f16(float* d, const uint32_t* a, const uint32_t* b) {
    asm volatile(
        "mma.sync.aligned.m16n8k16.row.col.f32.f16.f16.f32 "
        "{%0,%1,%2,%3}, {%4,%5,%6,%7}, {%8,%9}, {%0,%1,%2,%3};\n"
        : "+f"(d[0]), "+f"(d[1]), "+f"(d[2]), "+f"(d[3])
        : "r"(a[0]), "r"(a[1]), "r"(a[2]), "r"(a[3]),
          "r"(b[0]), "r"(b[1]));
}
__device__ __forceinline__ void ldsm4(uint32_t* r, uint32_t addr) {
    asm volatile("ldmatrix.sync.aligned.m8n8.x4.shared.b16 {%0,%1,%2,%3}, [%4];"
        : "=r"(r[0]), "=r"(r[1]), "=r"(r[2]), "=r"(r[3]) : "r"(addr));
}
__device__ __forceinline__ void ldsm4t(uint32_t* r, uint32_t addr) {
    asm volatile("ldmatrix.sync.aligned.m8n8.x4.trans.shared.b16 {%0,%1,%2,%3}, [%4];"
        : "=r"(r[0]), "=r"(r[1]), "=r"(r[2]), "=r"(r[3]) : "r"(addr));
}
__device__ __forceinline__ void sts32(uint32_t addr, uint32_t v) {
    asm volatile("st.shared.b32 [%0], %1;" :: "r"(addr), "r"(v) : "memory");
}
#define CPA16(dst, src) \
    asm volatile("cp.async.cg.shared.global [%0], [%1], 16;" \
        :: "r"(dst), "l"(src) : "memory")
#define CPA_COMMIT() asm volatile("cp.async.commit_group;" ::: "memory")

// Tile buffers: [rows][64 halfs] = 128B rows, 16B chunks XOR-swizzled by
// (row&7). kk16 step = address XOR (kk<<5).

// ===========================================================================
// Flash attention: 64 q-rows per block per (b,h). 256 threads, 8 warps in a
// 2x4 grid of 32x32 warp tiles. 2 CTAs/SM.
// smem: Q 2x8K @0 | P 2x8K @16K | stream 3x16K @32K | aux 1K @80K.
// Stream chunks (16KB, rows = 128 keys, cols = 64-hd half):
//   j in [0,64): tl=j>>2, cj=j&3; cj<2 -> K hd-half cj, else V hd-half cj-2.
// GEMM2 uses ldmatrix.trans on the V chunks (k-major) -- no Vt needed.
// ===========================================================================
static const int FLASH_SMEM = 82944;

__global__ void __launch_bounds__(256, 2) flash_attn(
    const __half* __restrict__ Q, const __half* __restrict__ Km,
    const __half* __restrict__ Vm, __half* __restrict__ Ctx)
{
    extern __shared__ float sm[];
    float* aux = sm + 20480;

    const int bh = blockIdx.y, b = bh >> 3, h = bh & 7;
    const int bm = blockIdx.x * 64;
    const int t = threadIdx.x, warp = t >> 5, lane = t & 31;
    const int wm = (warp & 1) * 32;        // q-rows (64 per CTA)
    const int wc = warp >> 1;              // key/hd column group (x32)
    const int wn = wc * 32;
    const int g = lane >> 2, tg = lane & 3;

    const uint32_t smb = smem_u32(sm);
    const int row0 = t >> 3, c0 = t & 7;   // row0 in [0,32)
    const uint32_t stOff = (uint32_t)(row0 * 128 + ((c0 ^ (row0 & 7)) << 4));

    const __half* Qg = Q  + (long long)b * 2097152 + h * 128
                     + (long long)(bm + row0) * 1024 + c0 * 8;
    const __half* Kg = Km + (long long)b * 2097152 + h * 128
                     + (long long)row0 * 1024 + c0 * 8;
    const __half* Vg = Vm + (long long)b * 2097152 + h * 128
                     + (long long)row0 * 1024 + c0 * 8;

    // Q: 2 sub-buffers (hd 0-63, 64-127), 64 rows each; rows row0, row0+32
    #pragma unroll
    for (int cq = 0; cq < 2; cq++) {
        CPA16(smb + cq * 8192u + stOff,         Qg + cq * 64);
        CPA16(smb + cq * 8192u + 4096u + stOff, Qg + 32768 + cq * 64);
    }
    CPA_COMMIT();

    // Unified K/V chunk: rows = keys tl*128..+127, cols = 64-hd half (cj&1)
    #define FETCH(j) do { \
        const int _tl = (j) >> 2, _cj = (j) & 3; \
        const uint32_t _dst = smb + 32768u + (uint32_t)((j) % 3) * 16384u + stOff; \
        const __half* _s = (_cj < 2 ? Kg : Vg) \
                         + (long long)(_tl * 128) * 1024 + (_cj & 1) * 64; \
        CPA16(_dst,           _s); \
        CPA16(_dst + 4096u,   _s + 32768); \
        CPA16(_dst + 8192u,   _s + 65536); \
        CPA16(_dst + 12288u,  _s + 98304); \
        CPA_COMMIT(); \
    } while (0)

    FETCH(0); FETCH(1);

    // ldmatrix lane-relative offsets
    uint32_t aRel[2], bRel[2], bRelT[2];
    {
        const int hiA = lane >> 4;
        #pragma unroll
        for (int mt = 0; mt < 2; mt++) {
            const int r = wm + mt * 16 + (lane & 15);   // [0,64)
            aRel[mt] = (uint32_t)((r << 7) + (((r & 7) ^ hiA) << 4));
        }
        const int quad = lane >> 3, l7 = lane & 7, hiB = quad & 1;
        #pragma unroll
        for (int j = 0; j < 2; j++) {
            const int nt = 2 * j + (quad >> 1);
            const int r = wn + nt * 8 + l7;             // key rows [0,128)
            bRel[j] = (uint32_t)((r << 7) + (((r & 7) ^ hiB) << 4));
        }
        // trans fragments for GEMM2: key rows r0 = (quad&1)*8 + l7,
        // hd 16B-chunk cI = cb + 2*j + (quad>>1); cb = warp's hd base / 8.
        const int r0 = (quad & 1) * 8 + l7;
        const int cb = (wn & 63) >> 3;
        #pragma unroll
        for (int j = 0; j < 2; j++) {
            const int cI = cb + 2 * j + (quad >> 1);
            bRelT[j] = (uint32_t)((r0 << 7) + ((cI ^ (r0 & 7)) << 4));
        }
    }

    float oacc[2][4][4];
    #pragma unroll
    for (int mt = 0; mt < 2; mt++)
        #pragma unroll
        for (int nt = 0; nt < 4; nt++)
            #pragma unroll
            for (int r = 0; r < 4; r++) oacc[mt][nt][r] = 0.0f;
    float lsum[2][2] = {{0.0f, 0.0f}, {0.0f, 0.0f}};

    const uint32_t pcBase = smb + 16384u + (uint32_t)(wc >> 1) * 8192u;
    const int gcOff = (wn & 32) >> 3;
    const int vHalf = wc >> 1;             // which V chunk this warp consumes

    #pragma unroll 1
    for (int tl = 0; tl < 16; tl++) {
        float sacc[2][4][4];
        #pragma unroll
        for (int mt = 0; mt < 2; mt++)
            #pragma unroll
            for (int nt = 0; nt < 4; nt++)
                #pragma unroll
                for (int r = 0; r < 4; r++) sacc[mt][nt][r] = 0.0f;

        // ---- GEMM1: S = Q @ K_tile^T  (hd halves cc = 0,1) ----
        #pragma unroll
        for (int cc = 0; cc < 2; cc++) {
            const int j = tl * 4 + cc;
            if (j < 63) asm volatile("cp.async.wait_group 1;" ::: "memory");
            else        asm volatile("cp.async.wait_group 0;" ::: "memory");
            __syncthreads();
            const uint32_t sOff = smb + 32768u + (uint32_t)(j % 3) * 16384u;
            const uint32_t aOff = smb + (uint32_t)cc * 8192u;
            #pragma unroll
            for (int kk = 0; kk < 4; kk++) {
                const uint32_t kx = (uint32_t)kk << 5;
                uint32_t bf[2][4];
                #pragma unroll
                for (int jj = 0; jj < 2; jj++)
                    ldsm4(bf[jj], (bRel[jj] + sOff) ^ kx);
                uint32_t af[2][4];
                #pragma unroll
                for (int mt = 0; mt < 2; mt++)
                    ldsm4(af[mt], (aRel[mt] + aOff) ^ kx);
                #pragma unroll
                for (int mt = 0; mt < 2; mt++)
                    #pragma unroll
                    for (int nt = 0; nt < 4; nt++)
                        mma_f16(sacc[mt][nt], af[mt], &bf[nt >> 1][(nt & 1) * 2]);
            }
            if (j + 2 < 64) FETCH(j + 2);
        }

        // ---- P = half(exp(S/32)) -> smem; accumulate rounded row sums ----
        #pragma unroll
        for (int mt = 0; mt < 2; mt++) {
            #pragma unroll
            for (int nt = 0; nt < 4; nt++) {
                const float p0 = __expf(sacc[mt][nt][0] * 0.03125f);
                const float p1 = __expf(sacc[mt][nt][1] * 0.03125f);
                const float p2 = __expf(sacc[mt][nt][2] * 0.03125f);
                const float p3 = __expf(sacc[mt][nt][3] * 0.03125f);
                __half2 h01 = __floats2half2_rn(p0, p1);
                __half2 h23 = __floats2half2_rn(p2, p3);
                const float2 b01 = __half22float2(h01);
                const float2 b23 = __half22float2(h23);
                lsum[mt][0] += b01.x + b01.y;
                lsum[mt][1] += b23.x + b23.y;
                const uint32_t gc = (uint32_t)(gcOff + nt);
                const int r0 = wm + mt * 16 + g, r1 = r0 + 8;
                sts32(pcBase + (uint32_t)(r0 << 7)
                             + ((gc ^ (uint32_t)(r0 & 7)) << 4) + (tg << 2),
                      *(uint32_t*)&h01);
                sts32(pcBase + (uint32_t)(r1 << 7)
                             + ((gc ^ (uint32_t)(r1 & 7)) << 4) + (tg << 2),
                      *(uint32_t*)&h23);
            }
        }

        // ---- GEMM2: O += P @ V_tile  (V hd-half chunks cc = 0,1) ----
        // Warp consumes only its own hd-half chunk, running all 128 keys.
        #pragma unroll
        for (int cc = 0; cc < 2; cc++) {
            const int j = tl * 4 + 2 + cc;
            if (j < 63) asm volatile("cp.async.wait_group 1;" ::: "memory");
            else        asm volatile("cp.async.wait_group 0;" ::: "memory");
            __syncthreads();   // also orders P stores above vs reads below
            if (vHalf == cc) {
                const uint32_t sOff = smb + 32768u + (uint32_t)(j % 3) * 16384u;
                #pragma unroll
                for (int kk = 0; kk < 8; kk++) {
                    uint32_t bf[2][4];
                    #pragma unroll
                    for (int jj = 0; jj < 2; jj++)
                        ldsm4t(bf[jj], bRelT[jj] + sOff + (uint32_t)kk * 2048u);
                    uint32_t af[2][4];
                    const uint32_t aOff = smb + 16384u + (uint32_t)(kk >> 2) * 8192u;
                    const uint32_t kx = (uint32_t)(kk & 3) << 5;
                    #pragma unroll
                    for (int mt = 0; mt < 2; mt++)
                        ldsm4(af[mt], (aRel[mt] + aOff) ^ kx);
                    #pragma unroll
                    for (int mt = 0; mt < 2; mt++)
                        #pragma unroll
                        for (int nt = 0; nt < 4; nt++)
                            mma_f16(oacc[mt][nt], af[mt], &bf[nt >> 1][(nt & 1) * 2]);
                }
            }
            if (j + 2 < 64) FETCH(j + 2);
        }
    }

    // ---- normalize O by row sums (4 warp-columns), write Ctx (fp16) ----
    #pragma unroll
    for (int mt = 0; mt < 2; mt++)
        #pragma unroll
        for (int rh = 0; rh < 2; rh++) {
            float v = lsum[mt][rh];
            v += __shfl_xor_sync(0xFFFFFFFFu, v, 1);
            v += __shfl_xor_sync(0xFFFFFFFFu, v, 2);
            if (tg == 0) aux[wc * 64 + wm + mt * 16 + rh * 8 + g] = v;
        }
    __syncthreads();
    float inv[2][2];
    #pragma unroll
    for (int mt = 0; mt < 2; mt++)
        #pragma unroll
        for (int rh = 0; rh < 2; rh++) {
            const int r = wm + mt * 16 + rh * 8 + g;
            inv[mt][rh] = 1.0f / (aux[r] + aux[64 + r] + aux[128 + r] + aux[192 + r]);
        }

    __half* Cb = Ctx + (long long)b * 2097152 + h * 128 + (long long)bm * 1024;
    #pragma unroll
    for (int mt = 0; mt < 2; mt++) {
        #pragma unroll
        for (int nt = 0; nt < 4; nt++) {
            const int m = wm + mt * 16 + g;
            const int n = wn + nt * 8 + tg * 2;
            __half2 lo = __floats2half2_rn(oacc[mt][nt][0] * inv[mt][0],
                                           oacc[mt][nt][1] * inv[mt][0]);
            __half2 hi = __floats2half2_rn(oacc[mt][nt][2] * inv[mt][1],
                                           oacc[mt][nt][3] * inv[mt][1]);
            *(__half2*)(Cb + (long long)m * 1024 + n)       = lo;
            *(__half2*)(Cb + (long long)(m + 8) * 1024 + n) = hi;
        }
    }
    #undef FETCH
}

// ===========================================================================
// TN GEMM (projections / FC), fp16 operands, f32 acc. 3-stage cp.async,
// ldmatrix.x4, 128x128 tile, k-tiles of 64, 256 threads, 2 CTAs/SM.
// ===========================================================================
static const int GEMM_SMEM = 98304;   // 3 x (16K A + 16K B)

template<bool OUT_HALF>
__global__ void __launch_bounds__(256, 2) gemm_h(
    const __half* __restrict__ A, const __half* __restrict__ Bm,
    void* __restrict__ Cv, const float* __restrict__ bias,
    int K, int lda, int ldb, int ldc,
    long long sA1, long long sB1, long long sC1, long long sBias)
{
    extern __shared__ float sm[];
    const int z = blockIdx.z;
    A  += (long long)z * sA1;
    Bm += (long long)z * sB1;
    const int bm = blockIdx.y * 128;
    const int bn = blockIdx.x * 128;

    const int t = threadIdx.x, warp = t >> 5, lane = t & 31;
    const int wm = (warp >> 1) * 32;
    const int wn = (warp & 1) * 64;
    const int g = lane >> 2, tg = lane & 3;

    const int row = t >> 3, c = t & 7;
    const __half* Ag = A  + (long long)(bm + row) * lda + c * 8;
    const __half* Bg = Bm + (long long)(bn + row) * ldb + c * 8;
    const uint32_t smb = smem_u32(sm);
    const uint32_t stOff = (uint32_t)(row * 128 + ((c ^ (row & 7)) << 4));
    const uint32_t aSt = smb + stOff;            // + stage*32768
    const uint32_t bSt = smb + 16384u + stOff;

    uint32_t aRel[2], bRel[4];
    {
        const int hiA = lane >> 4;
        #pragma unroll
        for (int mt = 0; mt < 2; mt++) {
            const int r = wm + mt * 16 + (lane & 15);
            aRel[mt] = (uint32_t)((r << 7) + (((r & 7) ^ hiA) << 4));
        }
        const int quad = lane >> 3, l7 = lane & 7, hiB = quad & 1;
        #pragma unroll
        for (int j = 0; j < 4; j++) {
            const int nt = 2 * j + (quad >> 1);
            const int r = wn + nt * 8 + l7;
            bRel[j] = (uint32_t)(16384 + (r << 7) + (((r & 7) ^ hiB) << 4));
        }
    }

    const int nk = K >> 6;
    #pragma unroll
    for (int s = 0; s < 2; s++) {
        const int kt = s << 6;
        #pragma unroll
        for (int i = 0; i < 4; i++) {
            CPA16(aSt + s * 32768u + i * 4096u, Ag + (long long)i * 32 * lda + kt);
            CPA16(bSt + s * 32768u + i * 4096u, Bg + (long long)i * 32 * ldb + kt);
        }
        CPA_COMMIT();
    }

    float acc[2][8][4];
    #pragma unroll
    for (int mt = 0; mt < 2; mt++)
        #pragma unroll
        for (int nt = 0; nt < 8; nt++)
            #pragma unroll
            for (int r = 0; r < 4; r++) acc[mt][nt][r] = 0.0f;

    int st = 0;
    for (int it = 0; it < nk; it++) {
        if (it + 1 < nk) asm volatile("cp.async.wait_group 1;" ::: "memory");
        else             asm volatile("cp.async.wait_group 0;" ::: "memory");
        __syncthreads();

        const uint32_t sOff = smb + (uint32_t)st * 32768u;
        #pragma unroll
        for (int kk = 0; kk < 4; kk++) {
            const uint32_t kx = (uint32_t)kk << 5;
            uint32_t bf[4][4];
            #pragma unroll
            for (int j = 0; j < 4; j++)
                ldsm4(bf[j], (bRel[j] + sOff) ^ kx);
            uint32_t af[2][4];
            #pragma unroll
            for (int mt = 0; mt < 2; mt++)
                ldsm4(af[mt], (aRel[mt] + sOff) ^ kx);
            #pragma unroll
            for (int mt = 0; mt < 2; mt++)
                #pragma unroll
                for (int nt = 0; nt < 8; nt++)
                    mma_f16(acc[mt][nt], af[mt], &bf[nt >> 1][(nt & 1) * 2]);
        }

        if (it + 2 < nk) {
            const int s2 = (st + 2) % 3;
            const int kt = (it + 2) << 6;
            #pragma unroll
            for (int i = 0; i < 4; i++) {
                CPA16(aSt + s2 * 32768u + i * 4096u, Ag + (long long)i * 32 * lda + kt);
                CPA16(bSt + s2 * 32768u + i * 4096u, Bg + (long long)i * 32 * ldb + kt);
            }
            CPA_COMMIT();
        }
        st = (st + 1) % 3;
    }

    #pragma unroll
    for (int mt = 0; mt < 2; mt++) {
        #pragma unroll
        for (int nt = 0; nt < 8; nt++) {
            const int m = bm + wm + mt * 16 + g;
            const int n = bn + wn + nt * 8 + tg * 2;
            const float bv0 = bias ? bias[z * sBias + n]     : 0.0f;
            const float bv1 = bias ? bias[z * sBias + n + 1] : 0.0f;
            const float v0 = acc[mt][nt][0] + bv0;
            const float v1 = acc[mt][nt][1] + bv1;
            const float v2 = acc[mt][nt][2] + bv0;
            const float v3 = acc[mt][nt][3] + bv1;
            if (OUT_HALF) {
                __half* C = (__half*)Cv + (long long)z * sC1;
                *(__half2*)(C + (long long)m * ldc + n)
                    = __floats2half2_rn(v0, v1);
                *(__half2*)(C + (long long)(m + 8) * ldc + n)
                    = __floats2half2_rn(v2, v3);
            } else {
                float* C = (float*)Cv + (long long)z * sC1;
                float2 r0v; r0v.x = v0; r0v.y = v1;
                float2 r1v; r1v.x = v2; r1v.y = v3;
                *(float2*)(C + (long long)m * ldc + n)       = r0v;
                *(float2*)(C + (long long)(m + 8) * ldc + n) = r1v;
            }
        }
    }
}

// All 7 float->fp16 conversions + bias staging in one launch.
// 4096 floats per block, 16 per thread (4 front-batched float4 loads).
__global__ void __launch_bounds__(256) round_all(
    const float* __restrict__ s0, const float* __restrict__ s1,
    const float* __restrict__ s2, const float* __restrict__ s3,
    const float* __restrict__ s4, const float* __restrict__ s5,
    const float* __restrict__ s6,
    const float* __restrict__ bq, const float* __restrict__ bk,
    const float* __restrict__ bv,
    __half* __restrict__ Inh, __half* __restrict__ Wh,
    float* __restrict__ Bias)
{
    const int bx = blockIdx.x;
    if (bx >= 8960) {
        const int idx = (bx - 8960) * 4096 + threadIdx.x * 16;
        const int seg = idx >> 13, o = idx & 8191;
        const float* src = (seg == 0) ? bq : (seg == 1) ? bk : bv;
        float4 v[4];
        #pragma unroll
        for (int i = 0; i < 4; i++) v[i] = *(const float4*)(src + o + i * 4);
        #pragma unroll
        for (int i = 0; i < 4; i++) *(float4*)(Bias + idx + i * 4) = v[i];
        return;
    }
    const float* src; __half* dst; int base;
    if (bx < 768) {
        const int seg = bx >> 8;
        src = (seg == 0) ? s0 : (seg == 1) ? s1 : s2;
        dst = Inh + seg * 1048576;
        base = (bx & 255) * 4096;
    } else {
        const int b2 = bx - 768;
        const int seg = b2 >> 11;
        src = (seg == 0) ? s3 : (seg == 1) ? s4 : (seg == 2) ? s5 : s6;
        dst = Wh + seg * 8388608;
        base = (b2 & 2047) * 4096;
    }
    const int i = base + threadIdx.x * 16;
    float4 v[4];
    #pragma unroll
    for (int j = 0; j < 4; j++) v[j] = *(const float4*)(src + i + j * 4);
    uint4 o[2];
    #pragma unroll
    for (int j = 0; j < 2; j++) {
        __half2 h0 = __floats2half2_rn(v[2*j].x,   v[2*j].y);
        __half2 h1 = __floats2half2_rn(v[2*j].z,   v[2*j].w);
        __half2 h2 = __floats2half2_rn(v[2*j+1].x, v[2*j+1].y);
        __half2 h3 = __floats2half2_rn(v[2*j+1].z, v[2*j+1].w);
        o[j].x = *(uint32_t*)&h0; o[j].y = *(uint32_t*)&h1;
        o[j].z = *(uint32_t*)&h2; o[j].w = *(uint32_t*)&h3;
    }
    *(uint4*)(dst + i)     = o[0];
    *(uint4*)(dst + i + 8) = o[1];
}

__global__ void __launch_bounds__(256) fc_reduce(
    const float* __restrict__ P, const float* __restrict__ bias,
    float* __restrict__ out)
{
    const int base = (blockIdx.x * 256 + threadIdx.x) * 4;
    const float4 a = *(const float4*)(P + base);
    const float4 b = *(const float4*)(P + base + 1048576);
    const float4 c = *(const float4*)(P + base + 2097152);
    const float4 d = *(const float4*)(P + base + 3145728);
    const float4 bi = *(const float4*)(bias + (base & 1023));
    float4 o;
    o.x = a.x + b.x + c.x + d.x + bi.x;
    o.y = a.y + b.y + c.y + d.y + bi.y;
    o.z = a.z + b.z + c.z + d.z + bi.z;
    o.w = a.w + b.w + c.w + d.w + bi.w;
    *(float4*)(out + base) = o;
}

extern "C" void kernel_launch(void* const* d_in, const int* in_sizes, int n_in,
                              void* d_out, int out_size)
{
    (void)in_sizes; (void)n_in; (void)out_size;
    const float* query = (const float*)d_in[0];
    const float* key_  = (const float*)d_in[1];
    const float* value = (const float*)d_in[2];
    const float* Wq    = (const float*)d_in[3];
    const float* bq    = (const float*)d_in[4];
    const float* Wk    = (const float*)d_in[5];
    const float* bk    = (const float*)d_in[6];
    const float* Wv    = (const float*)d_in[7];
    const float* bv    = (const float*)d_in[8];
    const float* Wfc   = (const float*)d_in[9];
    const float* bfc   = (const float*)d_in[10];
    float* out = (float*)d_out;

    __half *QKV, *Ctx, *Inh, *Wh;
    float *P, *Bias;
    cudaGetSymbolAddress((void**)&QKV, g_QKV);
    cudaGetSymbolAddress((void**)&Ctx, g_Ctx);
    cudaGetSymbolAddress((void**)&P,   g_P);
    cudaGetSymbolAddress((void**)&Inh, g_inh);
    cudaGetSymbolAddress((void**)&Wh,  g_Wh);
    cudaGetSymbolAddress((void**)&Bias, g_bias);

    cudaFuncSetAttribute((const void*)gemm_h<true>,  cudaFuncAttributeMaxDynamicSharedMemorySize, GEMM_SMEM);
    cudaFuncSetAttribute((const void*)gemm_h<false>, cudaFuncAttributeMaxDynamicSharedMemorySize, GEMM_SMEM);
    cudaFuncSetAttribute(flash_attn, cudaFuncAttributeMaxDynamicSharedMemorySize, FLASH_SMEM);

    const dim3 blk(256);

    // 0) fp16 conversions + bias staging (one launch)
    round_all<<<8966, blk>>>(query, key_, value, Wq, Wk, Wv, Wfc,
                             bq, bk, bv, Inh, Wh, Bias);

    // 1) Projections (z=3): M=1024, N=8192, K=1024 -> QKV (fp16)
    gemm_h<true><<<dim3(64, 8, 3), blk, GEMM_SMEM>>>(
        Inh, Wh, QKV, Bias, 1024, 1024, 1024, 8192,
        1048576LL, 8388608LL, 8388608LL, 8192LL);

    // 2) Fused flash attention -> Ctx (fp16); V read directly (ldsm.trans)
    flash_attn<<<dim3(32, 32), blk, FLASH_SMEM>>>(
        QKV, QKV + 8388608, QKV + 16777216, Ctx);

    // 3) FC split-K x4 (f32 partials), then reduce + bias
    gemm_h<false><<<dim3(8, 8, 4), blk, GEMM_SMEM>>>(
        Ctx, Wh + 25165824, P, nullptr, 2048, 8192, 8192, 1024,
        2048LL, 2048LL, 1048576LL, 0LL);
    fc_reduce<<<1024, blk>>>(P, bfc, out);
}

// round 17
// speedup vs baseline: 1.0158x; 1.0158x over previous
#include <cuda_runtime.h>
#include <cuda_fp16.h>
#include <cstdint>

// ---------------------------------------------------------------------------
// SelfAttention (B=4, S=256, HID=1024, NH=8) -> effective attn seq 2048, HD=128
// Round 17: R16 + (a) Q pre-scaled by 1/32 in projection epilogue (power-of-2,
// bit-exact; removes FMULs from flash P-burst), (b) lsum from pre-rounding
// exp values (removes unpack cvts). fp16 mma.m16n8k16, f32 accumulate.
// ---------------------------------------------------------------------------

__device__ __half g_QKV[25165824];  // Q | K | V, each (4,2048,8,128); Q /32
__device__ __half g_Ctx[8388608];
__device__ float  g_P[4194304];     // FC split-K partials
__device__ __half g_inh[3145728];   // fp16 query/key_/value
__device__ __half g_Wh[33554432];   // fp16 Wq,Wk,Wv,Wfc
__device__ float  g_bias[24576];    // bq | bk | bv

__device__ __forceinline__ uint32_t smem_u32(const void* p) {
    uint32_t a;
    asm("{ .reg .u64 t; cvta.to.shared.u64 t, %1; cvt.u32.u64 %0, t; }"
        : "=r"(a) : "l"(p));
    return a;
}
__device__ __forceinline__ void mma_f16(float* d, const uint32_t* a, const uint32_t* b) {
    asm volatile(
        "mma.sync.aligned.m16n8k16.row.col.f32.f16.f16.f32 "
        "{%0,%1,%2,%3}, {%4,%5,%6,%7}, {%8,%9}, {%0,%1,%2,%3};\n"
        : "+f"(d[0]), "+f"(d[1]), "+f"(d[2]), "+f"(d[3])
        : "r"(a[0]), "r"(a[1]), "r"(a[2]), "r"(a[3]),
          "r"(b[0]), "r"(b[1]));
}
__device__ __forceinline__ void ldsm4(uint32_t* r, uint32_t addr) {
    asm volatile("ldmatrix.sync.aligned.m8n8.x4.shared.b16 {%0,%1,%2,%3}, [%4];"
        : "=r"(r[0]), "=r"(r[1]), "=r"(r[2]), "=r"(r[3]) : "r"(addr));
}
__device__ __forceinline__ void ldsm4t(uint32_t* r, uint32_t addr) {
    asm volatile("ldmatrix.sync.aligned.m8n8.x4.trans.shared.b16 {%0,%1,%2,%3}, [%4];"
        : "=r"(r[0]), "=r"(r[1]), "=r"(r[2]), "=r"(r[3]) : "r"(addr));
}
__device__ __forceinline__ void sts32(uint32_t addr, uint32_t v) {
    asm volatile("st.shared.b32 [%0], %1;" :: "r"(addr), "r"(v) : "memory");
}
#define CPA16(dst, src) \
    asm volatile("cp.async.cg.shared.global [%0], [%1], 16;" \
        :: "r"(dst), "l"(src) : "memory")
#define CPA_COMMIT() asm volatile("cp.async.commit_group;" ::: "memory")

// Tile buffers: [rows][64 halfs] = 128B rows, 16B chunks XOR-swizzled by
// (row&7). kk16 step = address XOR (kk<<5).

// ===========================================================================
// Flash attention: 64 q-rows per block per (b,h). 256 threads, 8 warps in a
// 2x4 grid of 32x32 warp tiles. 2 CTAs/SM.
// smem: Q 2x8K @0 | P 2x8K @16K | stream 3x16K @32K | aux 1K @80K.
// Stream chunks (16KB, rows = 128 keys, cols = 64-hd half):
//   j in [0,64): tl=j>>2, cj=j&3; cj<2 -> K hd-half cj, else V hd-half cj-2.
// GEMM2 uses ldmatrix.trans on the V chunks (k-major) -- no Vt needed.
// Q arrives pre-scaled by 1/32, so logits = S directly.
// ===========================================================================
static const int FLASH_SMEM = 82944;

__global__ void __launch_bounds__(256, 2) flash_attn(
    const __half* __restrict__ Q, const __half* __restrict__ Km,
    const __half* __restrict__ Vm, __half* __restrict__ Ctx)
{
    extern __shared__ float sm[];
    float* aux = sm + 20480;

    const int bh = blockIdx.y, b = bh >> 3, h = bh & 7;
    const int bm = blockIdx.x * 64;
    const int t = threadIdx.x, warp = t >> 5, lane = t & 31;
    const int wm = (warp & 1) * 32;        // q-rows (64 per CTA)
    const int wc = warp >> 1;              // key/hd column group (x32)
    const int wn = wc * 32;
    const int g = lane >> 2, tg = lane & 3;

    const uint32_t smb = smem_u32(sm);
    const int row0 = t >> 3, c0 = t & 7;   // row0 in [0,32)
    const uint32_t stOff = (uint32_t)(row0 * 128 + ((c0 ^ (row0 & 7)) << 4));

    const __half* Qg = Q  + (long long)b * 2097152 + h * 128
                     + (long long)(bm + row0) * 1024 + c0 * 8;
    const __half* Kg = Km + (long long)b * 2097152 + h * 128
                     + (long long)row0 * 1024 + c0 * 8;
    const __half* Vg = Vm + (long long)b * 2097152 + h * 128
                     + (long long)row0 * 1024 + c0 * 8;

    // Q: 2 sub-buffers (hd 0-63, 64-127), 64 rows each; rows row0, row0+32
    #pragma unroll
    for (int cq = 0; cq < 2; cq++) {
        CPA16(smb + cq * 8192u + stOff,         Qg + cq * 64);
        CPA16(smb + cq * 8192u + 4096u + stOff, Qg + 32768 + cq * 64);
    }
    CPA_COMMIT();

    // Unified K/V chunk: rows = keys tl*128..+127, cols = 64-hd half (cj&1)
    #define FETCH(j) do { \
        const int _tl = (j) >> 2, _cj = (j) & 3; \
        const uint32_t _dst = smb + 32768u + (uint32_t)((j) % 3) * 16384u + stOff; \
        const __half* _s = (_cj < 2 ? Kg : Vg) \
                         + (long long)(_tl * 128) * 1024 + (_cj & 1) * 64; \
        CPA16(_dst,           _s); \
        CPA16(_dst + 4096u,   _s + 32768); \
        CPA16(_dst + 8192u,   _s + 65536); \
        CPA16(_dst + 12288u,  _s + 98304); \
        CPA_COMMIT(); \
    } while (0)

    FETCH(0); FETCH(1);

    // ldmatrix lane-relative offsets
    uint32_t aRel[2], bRel[2], bRelT[2];
    {
        const int hiA = lane >> 4;
        #pragma unroll
        for (int mt = 0; mt < 2; mt++) {
            const int r = wm + mt * 16 + (lane & 15);   // [0,64)
            aRel[mt] = (uint32_t)((r << 7) + (((r & 7) ^ hiA) << 4));
        }
        const int quad = lane >> 3, l7 = lane & 7, hiB = quad & 1;
        #pragma unroll
        for (int j = 0; j < 2; j++) {
            const int nt = 2 * j + (quad >> 1);
            const int r = wn + nt * 8 + l7;             // key rows [0,128)
            bRel[j] = (uint32_t)((r << 7) + (((r & 7) ^ hiB) << 4));
        }
        // trans fragments for GEMM2: key rows r0 = (quad&1)*8 + l7,
        // hd 16B-chunk cI = cb + 2*j + (quad>>1); cb = warp's hd base / 8.
        const int r0 = (quad & 1) * 8 + l7;
        const int cb = (wn & 63) >> 3;
        #pragma unroll
        for (int j = 0; j < 2; j++) {
            const int cI = cb + 2 * j + (quad >> 1);
            bRelT[j] = (uint32_t)((r0 << 7) + ((cI ^ (r0 & 7)) << 4));
        }
    }

    float oacc[2][4][4];
    #pragma unroll
    for (int mt = 0; mt < 2; mt++)
        #pragma unroll
        for (int nt = 0; nt < 4; nt++)
            #pragma unroll
            for (int r = 0; r < 4; r++) oacc[mt][nt][r] = 0.0f;
    float lsum[2][2] = {{0.0f, 0.0f}, {0.0f, 0.0f}};

    const uint32_t pcBase = smb + 16384u + (uint32_t)(wc >> 1) * 8192u;
    const int gcOff = (wn & 32) >> 3;
    const int vHalf = wc >> 1;             // which V chunk this warp consumes

    #pragma unroll 1
    for (int tl = 0; tl < 16; tl++) {
        float sacc[2][4][4];
        #pragma unroll
        for (int mt = 0; mt < 2; mt++)
            #pragma unroll
            for (int nt = 0; nt < 4; nt++)
                #pragma unroll
                for (int r = 0; r < 4; r++) sacc[mt][nt][r] = 0.0f;

        // ---- GEMM1: S = Q @ K_tile^T  (hd halves cc = 0,1) ----
        #pragma unroll
        for (int cc = 0; cc < 2; cc++) {
            const int j = tl * 4 + cc;
            if (j < 63) asm volatile("cp.async.wait_group 1;" ::: "memory");
            else        asm volatile("cp.async.wait_group 0;" ::: "memory");
            __syncthreads();
            const uint32_t sOff = smb + 32768u + (uint32_t)(j % 3) * 16384u;
            const uint32_t aOff = smb + (uint32_t)cc * 8192u;
            #pragma unroll
            for (int kk = 0; kk < 4; kk++) {
                const uint32_t kx = (uint32_t)kk << 5;
                uint32_t bf[2][4];
                #pragma unroll
                for (int jj = 0; jj < 2; jj++)
                    ldsm4(bf[jj], (bRel[jj] + sOff) ^ kx);
                uint32_t af[2][4];
                #pragma unroll
                for (int mt = 0; mt < 2; mt++)
                    ldsm4(af[mt], (aRel[mt] + aOff) ^ kx);
                #pragma unroll
                for (int mt = 0; mt < 2; mt++)
                    #pragma unroll
                    for (int nt = 0; nt < 4; nt++)
                        mma_f16(sacc[mt][nt], af[mt], &bf[nt >> 1][(nt & 1) * 2]);
            }
            if (j + 2 < 64) FETCH(j + 2);
        }

        // ---- P = half(exp(S)) -> smem; accumulate row sums ----
        #pragma unroll
        for (int mt = 0; mt < 2; mt++) {
            #pragma unroll
            for (int nt = 0; nt < 4; nt++) {
                const float p0 = __expf(sacc[mt][nt][0]);
                const float p1 = __expf(sacc[mt][nt][1]);
                const float p2 = __expf(sacc[mt][nt][2]);
                const float p3 = __expf(sacc[mt][nt][3]);
                lsum[mt][0] += p0 + p1;
                lsum[mt][1] += p2 + p3;
                __half2 h01 = __floats2half2_rn(p0, p1);
                __half2 h23 = __floats2half2_rn(p2, p3);
                const uint32_t gc = (uint32_t)(gcOff + nt);
                const int r0 = wm + mt * 16 + g, r1 = r0 + 8;
                sts32(pcBase + (uint32_t)(r0 << 7)
                             + ((gc ^ (uint32_t)(r0 & 7)) << 4) + (tg << 2),
                      *(uint32_t*)&h01);
                sts32(pcBase + (uint32_t)(r1 << 7)
                             + ((gc ^ (uint32_t)(r1 & 7)) << 4) + (tg << 2),
                      *(uint32_t*)&h23);
            }
        }

        // ---- GEMM2: O += P @ V_tile  (V hd-half chunks cc = 0,1) ----
        #pragma unroll
        for (int cc = 0; cc < 2; cc++) {
            const int j = tl * 4 + 2 + cc;
            if (j < 63) asm volatile("cp.async.wait_group 1;" ::: "memory");
            else        asm volatile("cp.async.wait_group 0;" ::: "memory");
            __syncthreads();   // also orders P stores above vs reads below
            if (vHalf == cc) {
                const uint32_t sOff = smb + 32768u + (uint32_t)(j % 3) * 16384u;
                #pragma unroll
                for (int kk = 0; kk < 8; kk++) {
                    uint32_t bf[2][4];
                    #pragma unroll
                    for (int jj = 0; jj < 2; jj++)
                        ldsm4t(bf[jj], bRelT[jj] + sOff + (uint32_t)kk * 2048u);
                    uint32_t af[2][4];
                    const uint32_t aOff = smb + 16384u + (uint32_t)(kk >> 2) * 8192u;
                    const uint32_t kx = (uint32_t)(kk & 3) << 5;
                    #pragma unroll
                    for (int mt = 0; mt < 2; mt++)
                        ldsm4(af[mt], (aRel[mt] + aOff) ^ kx);
                    #pragma unroll
                    for (int mt = 0; mt < 2; mt++)
                        #pragma unroll
                        for (int nt = 0; nt < 4; nt++)
                            mma_f16(oacc[mt][nt], af[mt], &bf[nt >> 1][(nt & 1) * 2]);
                }
            }
            if (j + 2 < 64) FETCH(j + 2);
        }
    }

    // ---- normalize O by row sums (4 warp-columns), write Ctx (fp16) ----
    #pragma unroll
    for (int mt = 0; mt < 2; mt++)
        #pragma unroll
        for (int rh = 0; rh < 2; rh++) {
            float v = lsum[mt][rh];
            v += __shfl_xor_sync(0xFFFFFFFFu, v, 1);
            v += __shfl_xor_sync(0xFFFFFFFFu, v, 2);
            if (tg == 0) aux[wc * 64 + wm + mt * 16 + rh * 8 + g] = v;
        }
    __syncthreads();
    float inv[2][2];
    #pragma unroll
    for (int mt = 0; mt < 2; mt++)
        #pragma unroll
        for (int rh = 0; rh < 2; rh++) {
            const int r = wm + mt * 16 + rh * 8 + g;
            inv[mt][rh] = 1.0f / (aux[r] + aux[64 + r] + aux[128 + r] + aux[192 + r]);
        }

    __half* Cb = Ctx + (long long)b * 2097152 + h * 128 + (long long)bm * 1024;
    #pragma unroll
    for (int mt = 0; mt < 2; mt++) {
        #pragma unroll
        for (int nt = 0; nt < 4; nt++) {
            const int m = wm + mt * 16 + g;
            const int n = wn + nt * 8 + tg * 2;
            __half2 lo = __floats2half2_rn(oacc[mt][nt][0] * inv[mt][0],
                                           oacc[mt][nt][1] * inv[mt][0]);
            __half2 hi = __floats2half2_rn(oacc[mt][nt][2] * inv[mt][1],
                                           oacc[mt][nt][3] * inv[mt][1]);
            *(__half2*)(Cb + (long long)m * 1024 + n)       = lo;
            *(__half2*)(Cb + (long long)(m + 8) * 1024 + n) = hi;
        }
    }
    #undef FETCH
}

// ===========================================================================
// TN GEMM (projections / FC), fp16 operands, f32 acc. 3-stage cp.async,
// ldmatrix.x4, 128x128 tile, k-tiles of 64, 256 threads, 2 CTAs/SM.
// OUT_HALF epilogue applies qscale when z==0 (exact power-of-2 Q pre-scale).
// ===========================================================================
static const int GEMM_SMEM = 98304;   // 3 x (16K A + 16K B)

template<bool OUT_HALF>
__global__ void __launch_bounds__(256, 2) gemm_h(
    const __half* __restrict__ A, const __half* __restrict__ Bm,
    void* __restrict__ Cv, const float* __restrict__ bias,
    int K, int lda, int ldb, int ldc,
    long long sA1, long long sB1, long long sC1, long long sBias,
    float qscale)
{
    extern __shared__ float sm[];
    const int z = blockIdx.z;
    A  += (long long)z * sA1;
    Bm += (long long)z * sB1;
    const int bm = blockIdx.y * 128;
    const int bn = blockIdx.x * 128;

    const int t = threadIdx.x, warp = t >> 5, lane = t & 31;
    const int wm = (warp >> 1) * 32;
    const int wn = (warp & 1) * 64;
    const int g = lane >> 2, tg = lane & 3;

    const int row = t >> 3, c = t & 7;
    const __half* Ag = A  + (long long)(bm + row) * lda + c * 8;
    const __half* Bg = Bm + (long long)(bn + row) * ldb + c * 8;
    const uint32_t smb = smem_u32(sm);
    const uint32_t stOff = (uint32_t)(row * 128 + ((c ^ (row & 7)) << 4));
    const uint32_t aSt = smb + stOff;            // + stage*32768
    const uint32_t bSt = smb + 16384u + stOff;

    uint32_t aRel[2], bRel[4];
    {
        const int hiA = lane >> 4;
        #pragma unroll
        for (int mt = 0; mt < 2; mt++) {
            const int r = wm + mt * 16 + (lane & 15);
            aRel[mt] = (uint32_t)((r << 7) + (((r & 7) ^ hiA) << 4));
        }
        const int quad = lane >> 3, l7 = lane & 7, hiB = quad & 1;
        #pragma unroll
        for (int j = 0; j < 4; j++) {
            const int nt = 2 * j + (quad >> 1);
            const int r = wn + nt * 8 + l7;
            bRel[j] = (uint32_t)(16384 + (r << 7) + (((r & 7) ^ hiB) << 4));
        }
    }

    const int nk = K >> 6;
    #pragma unroll
    for (int s = 0; s < 2; s++) {
        const int kt = s << 6;
        #pragma unroll
        for (int i = 0; i < 4; i++) {
            CPA16(aSt + s * 32768u + i * 4096u, Ag + (long long)i * 32 * lda + kt);
            CPA16(bSt + s * 32768u + i * 4096u, Bg + (long long)i * 32 * ldb + kt);
        }
        CPA_COMMIT();
    }

    float acc[2][8][4];
    #pragma unroll
    for (int mt = 0; mt < 2; mt++)
        #pragma unroll
        for (int nt = 0; nt < 8; nt++)
            #pragma unroll
            for (int r = 0; r < 4; r++) acc[mt][nt][r] = 0.0f;

    int st = 0;
    for (int it = 0; it < nk; it++) {
        if (it + 1 < nk) asm volatile("cp.async.wait_group 1;" ::: "memory");
        else             asm volatile("cp.async.wait_group 0;" ::: "memory");
        __syncthreads();

        const uint32_t sOff = smb + (uint32_t)st * 32768u;
        #pragma unroll
        for (int kk = 0; kk < 4; kk++) {
            const uint32_t kx = (uint32_t)kk << 5;
            uint32_t bf[4][4];
            #pragma unroll
            for (int j = 0; j < 4; j++)
                ldsm4(bf[j], (bRel[j] + sOff) ^ kx);
            uint32_t af[2][4];
            #pragma unroll
            for (int mt = 0; mt < 2; mt++)
                ldsm4(af[mt], (aRel[mt] + sOff) ^ kx);
            #pragma unroll
            for (int mt = 0; mt < 2; mt++)
                #pragma unroll
                for (int nt = 0; nt < 8; nt++)
                    mma_f16(acc[mt][nt], af[mt], &bf[nt >> 1][(nt & 1) * 2]);
        }

        if (it + 2 < nk) {
            const int s2 = (st + 2) % 3;
            const int kt = (it + 2) << 6;
            #pragma unroll
            for (int i = 0; i < 4; i++) {
                CPA16(aSt + s2 * 32768u + i * 4096u, Ag + (long long)i * 32 * lda + kt);
                CPA16(bSt + s2 * 32768u + i * 4096u, Bg + (long long)i * 32 * ldb + kt);
            }
            CPA_COMMIT();
        }
        st = (st + 1) % 3;
    }

    const float cs = (OUT_HALF && z == 0) ? qscale : 1.0f;
    #pragma unroll
    for (int mt = 0; mt < 2; mt++) {
        #pragma unroll
        for (int nt = 0; nt < 8; nt++) {
            const int m = bm + wm + mt * 16 + g;
            const int n = bn + wn + nt * 8 + tg * 2;
            const float bv0 = bias ? bias[z * sBias + n]     : 0.0f;
            const float bv1 = bias ? bias[z * sBias + n + 1] : 0.0f;
            const float v0 = (acc[mt][nt][0] + bv0) * cs;
            const float v1 = (acc[mt][nt][1] + bv1) * cs;
            const float v2 = (acc[mt][nt][2] + bv0) * cs;
            const float v3 = (acc[mt][nt][3] + bv1) * cs;
            if (OUT_HALF) {
                __half* C = (__half*)Cv + (long long)z * sC1;
                *(__half2*)(C + (long long)m * ldc + n)
                    = __floats2half2_rn(v0, v1);
                *(__half2*)(C + (long long)(m + 8) * ldc + n)
                    = __floats2half2_rn(v2, v3);
            } else {
                float* C = (float*)Cv + (long long)z * sC1;
                float2 r0v; r0v.x = v0; r0v.y = v1;
                float2 r1v; r1v.x = v2; r1v.y = v3;
                *(float2*)(C + (long long)m * ldc + n)       = r0v;
                *(float2*)(C + (long long)(m + 8) * ldc + n) = r1v;
            }
        }
    }
}

// All 7 float->fp16 conversions + bias staging in one launch.
// 4096 floats per block, 16 per thread (4 front-batched float4 loads).
__global__ void __launch_bounds__(256) round_all(
    const float* __restrict__ s0, const float* __restrict__ s1,
    const float* __restrict__ s2, const float* __restrict__ s3,
    const float* __restrict__ s4, const float* __restrict__ s5,
    const float* __restrict__ s6,
    const float* __restrict__ bq, const float* __restrict__ bk,
    const float* __restrict__ bv,
    __half* __restrict__ Inh, __half* __restrict__ Wh,
    float* __restrict__ Bias)
{
    const int bx = blockIdx.x;
    if (bx >= 8960) {
        const int idx = (bx - 8960) * 4096 + threadIdx.x * 16;
        const int seg = idx >> 13, o = idx & 8191;
        const float* src = (seg == 0) ? bq : (seg == 1) ? bk : bv;
        float4 v[4];
        #pragma unroll
        for (int i = 0; i < 4; i++) v[i] = *(const float4*)(src + o + i * 4);
        #pragma unroll
        for (int i = 0; i < 4; i++) *(float4*)(Bias + idx + i * 4) = v[i];
        return;
    }
    const float* src; __half* dst; int base;
    if (bx < 768) {
        const int seg = bx >> 8;
        src = (seg == 0) ? s0 : (seg == 1) ? s1 : s2;
        dst = Inh + seg * 1048576;
        base = (bx & 255) * 4096;
    } else {
        const int b2 = bx - 768;
        const int seg = b2 >> 11;
        src = (seg == 0) ? s3 : (seg == 1) ? s4 : (seg == 2) ? s5 : s6;
        dst = Wh + seg * 8388608;
        base = (b2 & 2047) * 4096;
    }
    const int i = base + threadIdx.x * 16;
    float4 v[4];
    #pragma unroll
    for (int j = 0; j < 4; j++) v[j] = *(const float4*)(src + i + j * 4);
    uint4 o[2];
    #pragma unroll
    for (int j = 0; j < 2; j++) {
        __half2 h0 = __floats2half2_rn(v[2*j].x,   v[2*j].y);
        __half2 h1 = __floats2half2_rn(v[2*j].z,   v[2*j].w);
        __half2 h2 = __floats2half2_rn(v[2*j+1].x, v[2*j+1].y);
        __half2 h3 = __floats2half2_rn(v[2*j+1].z, v[2*j+1].w);
        o[j].x = *(uint32_t*)&h0; o[j].y = *(uint32_t*)&h1;
        o[j].z = *(uint32_t*)&h2; o[j].w = *(uint32_t*)&h3;
    }
    *(uint4*)(dst + i)     = o[0];
    *(uint4*)(dst + i + 8) = o[1];
}

__global__ void __launch_bounds__(256) fc_reduce(
    const float* __restrict__ P, const float* __restrict__ bias,
    float* __restrict__ out)
{
    const int base = (blockIdx.x * 256 + threadIdx.x) * 4;
    const float4 a = *(const float4*)(P + base);
    const float4 b = *(const float4*)(P + base + 1048576);
    const float4 c = *(const float4*)(P + base + 2097152);
    const float4 d = *(const float4*)(P + base + 3145728);
    const float4 bi = *(const float4*)(bias + (base & 1023));
    float4 o;
    o.x = a.x + b.x + c.x + d.x + bi.x;
    o.y = a.y + b.y + c.y + d.y + bi.y;
    o.z = a.z + b.z + c.z + d.z + bi.z;
    o.w = a.w + b.w + c.w + d.w + bi.w;
    *(float4*)(out + base) = o;
}

extern "C" void kernel_launch(void* const* d_in, const int* in_sizes, int n_in,
                              void* d_out, int out_size)
{
    (void)in_sizes; (void)n_in; (void)out_size;
    const float* query = (const float*)d_in[0];
    const float* key_  = (const float*)d_in[1];
    const float* value = (const float*)d_in[2];
    const float* Wq    = (const float*)d_in[3];
    const float* bq    = (const float*)d_in[4];
    const float* Wk    = (const float*)d_in[5];
    const float* bk    = (const float*)d_in[6];
    const float* Wv    = (const float*)d_in[7];
    const float* bv    = (const float*)d_in[8];
    const float* Wfc   = (const float*)d_in[9];
    const float* bfc   = (const float*)d_in[10];
    float* out = (float*)d_out;

    __half *QKV, *Ctx, *Inh, *Wh;
    float *P, *Bias;
    cudaGetSymbolAddress((void**)&QKV, g_QKV);
    cudaGetSymbolAddress((void**)&Ctx, g_Ctx);
    cudaGetSymbolAddress((void**)&P,   g_P);
    cudaGetSymbolAddress((void**)&Inh, g_inh);
    cudaGetSymbolAddress((void**)&Wh,  g_Wh);
    cudaGetSymbolAddress((void**)&Bias, g_bias);

    cudaFuncSetAttribute((const void*)gemm_h<true>,  cudaFuncAttributeMaxDynamicSharedMemorySize, GEMM_SMEM);
    cudaFuncSetAttribute((const void*)gemm_h<false>, cudaFuncAttributeMaxDynamicSharedMemorySize, GEMM_SMEM);
    cudaFuncSetAttribute(flash_attn, cudaFuncAttributeMaxDynamicSharedMemorySize, FLASH_SMEM);

    const dim3 blk(256);

    // 0) fp16 conversions + bias staging (one launch)
    round_all<<<8966, blk>>>(query, key_, value, Wq, Wk, Wv, Wfc,
                             bq, bk, bv, Inh, Wh, Bias);

    // 1) Projections (z=3): M=1024, N=8192, K=1024 -> QKV (fp16); Q scaled /32
    gemm_h<true><<<dim3(64, 8, 3), blk, GEMM_SMEM>>>(
        Inh, Wh, QKV, Bias, 1024, 1024, 1024, 8192,
        1048576LL, 8388608LL, 8388608LL, 8192LL, 0.03125f);

    // 2) Fused flash attention -> Ctx (fp16); V read directly (ldsm.trans)
    flash_attn<<<dim3(32, 32), blk, FLASH_SMEM>>>(
        QKV, QKV + 8388608, QKV + 16777216, Ctx);

    // 3) FC split-K x4 (f32 partials), then reduce + bias
    gemm_h<false><<<dim3(8, 8, 4), blk, GEMM_SMEM>>>(
        Ctx, Wh + 25165824, P, nullptr, 2048, 8192, 8192, 1024,
        2048LL, 2048LL, 1048576LL, 0LL, 1.0f);
    fc_reduce<<<1024, blk>>>(P, bfc, out);
}